// round 9
// baseline (speedup 1.0000x reference)
#include <cuda_runtime.h>
#include <cuda_bf16.h>
#include <cstdint>

#define NB      1024
#define NNODES  10000
#define NROOTS  4
#define MNODES  (NNODES - NROOTS)   // 9996
#define NCONF   16
#define NRG     32
#define NPAD    10016

// Transposed bit-pack, rg-major: g_evt[rg*NPAD + n] bit r = ev[rg*32+r][n]
__device__ uint32_t g_evt[NRG * NPAD];       // 1.28 MB
__device__ float    g_sig[MNODES * NCONF];   // 640 KB pre-sigmoided CPT

// ---------------------------------------------------------------------------
// Kernel A (fused pack + sigmoid), unchanged from best version.
// ---------------------------------------------------------------------------
#define PACK_TILES   157                    // ceil(10000/64)
#define PACK_BLOCKS  (PACK_TILES * 32 / 8)  // 628
#define SIG_TOTAL    (MNODES * NCONF / 4)   // 39984 float4
#define SIG_BLOCKS   ((SIG_TOTAL + 255) / 256)

__global__ __launch_bounds__(256)
void pack_sig_kernel(const int* __restrict__ ev, const float4* __restrict__ cpt4) {
    if (blockIdx.x >= PACK_BLOCKS) {
        int idx = (blockIdx.x - PACK_BLOCKS) * 256 + threadIdx.x;
        if (idx < SIG_TOTAL) {
            float4 x = cpt4[idx];
            float4 y;
            y.x = 1.0f / (1.0f + __expf(-x.x));
            y.y = 1.0f / (1.0f + __expf(-x.y));
            y.z = 1.0f / (1.0f + __expf(-x.z));
            y.w = 1.0f / (1.0f + __expf(-x.w));
            ((float4*)g_sig)[idx] = y;
        }
        return;
    }

    const int g    = blockIdx.x * 8 + (threadIdx.x >> 5);
    const int lane = threadIdx.x & 31;
    const int rg   = g & 31;
    const int tile = g >> 5;                 // 0..156
    const int n    = tile * 64 + lane * 2;
    if (n >= NNODES) return;                 // NNODES even: pairs never straddle

    const int* __restrict__ base = ev + (size_t)(rg * 32) * NNODES + n;
    uint32_t a0 = 0, a1 = 0;
    #pragma unroll 8
    for (int r = 0; r < 32; r++) {
        int2 v = *(const int2*)(base + (size_t)r * NNODES);
        a0 |= (uint32_t)(v.x & 1) << r;
        a1 |= (uint32_t)(v.y & 1) << r;
    }
    *(uint2*)(g_evt + rg * NPAD + n) = make_uint2(a0, a1);
}

// ---------------------------------------------------------------------------
// 15-SEL binary tree: pick v[b3*8+b2*4+b1*2+b0] from 16 register-resident vals
// ---------------------------------------------------------------------------
__device__ __forceinline__ float sel16(const float v[16],
                                       bool b3, bool b2, bool b1, bool b0) {
    float t0 = b0 ? v[1]  : v[0];
    float t1 = b0 ? v[3]  : v[2];
    float t2 = b0 ? v[5]  : v[4];
    float t3 = b0 ? v[7]  : v[6];
    float t4 = b0 ? v[9]  : v[8];
    float t5 = b0 ? v[11] : v[10];
    float t6 = b0 ? v[13] : v[12];
    float t7 = b0 ? v[15] : v[14];
    float u0 = b1 ? t1 : t0;
    float u1 = b1 ? t3 : t2;
    float u2 = b1 ? t5 : t4;
    float u3 = b1 ? t7 : t6;
    float s0 = b2 ? u1 : u0;
    float s1 = b2 ? u3 : u2;
    return b3 ? s1 : s0;
}

// ---------------------------------------------------------------------------
// Kernel B: main, smem-free. grid=(20,32), block=256. Thread owns a node pair;
// 16+16 sigmoid values live in registers; per row: 8 ISETP + 30 FSEL + STG.64.
// ---------------------------------------------------------------------------
#define THREADS 256
#define NPAIR   (MNODES / 2)   // 4998

__global__ __launch_bounds__(THREADS)
void bayes_main(const int4*  __restrict__ parents4,
                const float* __restrict__ root_logits,
                float*       __restrict__ out) {
    const int rg  = blockIdx.y;
    const int b0  = rg * 32;
    const int tid = threadIdx.x;
    const int ip  = blockIdx.x * THREADS + tid;

    if (blockIdx.x == 0 && tid < 32 * NROOTS) {
        int r = tid & (NROOTS - 1), row = tid >> 2;
        float x = root_logits[r];
        out[(size_t)(b0 + row) * NNODES + r] = 1.0f / (1.0f + __expf(-x));
    }
    if (ip >= NPAIR) return;
    const int i0 = ip * 2;

    const uint32_t* __restrict__ evt = g_evt + rg * NPAD;
    const int4 pa = parents4[i0];
    const int4 pb = parents4[i0 + 1];
    // conf = bit(p0)<<3 | bit(p1)<<2 | bit(p2)<<1 | bit(p3)
    const uint32_t wa3 = evt[pa.x], wa2 = evt[pa.y], wa1 = evt[pa.z], wa0 = evt[pa.w];
    const uint32_t wb3 = evt[pb.x], wb2 = evt[pb.y], wb1 = evt[pb.z], wb0 = evt[pb.w];

    // Register-resident sigmoid tables for both nodes
    float A[16], B[16];
    {
        const float4* __restrict__ s = (const float4*)(g_sig + (size_t)i0 * NCONF);
        #pragma unroll
        for (int j = 0; j < 4; j++) {
            float4 a = s[j];
            A[4*j+0] = a.x; A[4*j+1] = a.y; A[4*j+2] = a.z; A[4*j+3] = a.w;
            float4 b = s[4 + j];
            B[4*j+0] = b.x; B[4*j+1] = b.y; B[4*j+2] = b.z; B[4*j+3] = b.w;
        }
    }

    float* obase = out + (size_t)b0 * NNODES + NROOTS + i0;
    #pragma unroll
    for (int r = 0; r < 32; r++) {
        const uint32_t m = 1u << r;          // literal mask per unrolled iter
        float fA = sel16(A, (wa3 & m) != 0, (wa2 & m) != 0,
                            (wa1 & m) != 0, (wa0 & m) != 0);
        float fB = sel16(B, (wb3 & m) != 0, (wb2 & m) != 0,
                            (wb1 & m) != 0, (wb0 & m) != 0);
        *(float2*)(obase + (size_t)r * NNODES) = make_float2(fA, fB);
    }
}

// ---------------------------------------------------------------------------
extern "C" void kernel_launch(void* const* d_in, const int* in_sizes, int n_in,
                              void* d_out, int out_size) {
    const int*    ev      = (const int*)d_in[0];
    const int4*   parents = (const int4*)d_in[1];
    const float*  roots   = (const float*)d_in[2];
    const float4* cpt4    = (const float4*)d_in[3];
    float*        out     = (float*)d_out;

    pack_sig_kernel<<<PACK_BLOCKS + SIG_BLOCKS, 256>>>(ev, cpt4);

    dim3 gmain((NPAIR + THREADS - 1) / THREADS, NRG);   // (20, 32)
    bayes_main<<<gmain, THREADS>>>(parents, roots, out);
}